// round 14
// baseline (speedup 1.0000x reference)
#include <cuda_runtime.h>
#include <cuda_bf16.h>
#include <stdint.h>

#define E_EXP 8
#define D_DIM 1024
#define F_DIM 4096
#define T_TOK 4096
#define NSLOT (T_TOK * 2)

// ---------------- scratch (static __device__ arrays; no allocation) ----------------
__device__ __nv_bfloat16 g_xa[(size_t)NSLOT * D_DIM];   // per-slot bf16(x * inv_rms * ln_w[e])
__device__ __nv_bfloat16 g_w1b[(size_t)E_EXP * F_DIM * D_DIM];
__device__ __nv_bfloat16 g_w3b[(size_t)E_EXP * F_DIM * D_DIM];
__device__ __nv_bfloat16 g_w2b[(size_t)E_EXP * D_DIM * F_DIM];
__device__ __nv_bfloat16 g_h[(size_t)NSLOT * F_DIM];
__device__ float         g_ys[(size_t)NSLOT * D_DIM];
__device__ float g_inv[T_TOK];
__device__ int   g_cnt[E_EXP];     // zero at load; re-zeroed by combine each call
__device__ int   g_off[E_EXP];
__device__ int   g_perm[NSLOT];
__device__ int   g_slotE[NSLOT];
__device__ int   g_tokE[NSLOT];
__device__ int   g_slot[NSLOT];
__device__ float g_gw[NSLOT];
__device__ int   g_cdone[E_EXP];   // conv completion counters (reset by combine)
__device__ int   g_flag[E_EXP];    // per-expert w1/w3 ready flags (reset by combine)

// ---------------- small helpers ----------------
__device__ __forceinline__ void cp16s(uint32_t dst, const void* src) {
    asm volatile("cp.async.cg.shared.global [%0], [%1], 16;\n" :: "r"(dst), "l"(src));
}
__device__ __forceinline__ void cp_commit() { asm volatile("cp.async.commit_group;\n" ::: "memory"); }
template <int N>
__device__ __forceinline__ void cp_wait() { asm volatile("cp.async.wait_group %0;\n" :: "n"(N) : "memory"); }

__device__ __forceinline__ void ldsm4(uint32_t* r, uint32_t a) {
    asm volatile("ldmatrix.sync.aligned.m8n8.x4.shared.b16 {%0,%1,%2,%3}, [%4];\n"
                 : "=r"(r[0]), "=r"(r[1]), "=r"(r[2]), "=r"(r[3]) : "r"(a));
}
__device__ __forceinline__ void mma16816(float* c, const uint32_t* a, uint32_t b0, uint32_t b1) {
    asm volatile(
        "mma.sync.aligned.m16n8k16.row.col.f32.bf16.bf16.f32 "
        "{%0,%1,%2,%3}, {%4,%5,%6,%7}, {%8,%9}, {%0,%1,%2,%3};\n"
        : "+f"(c[0]), "+f"(c[1]), "+f"(c[2]), "+f"(c[3])
        : "r"(a[0]), "r"(a[1]), "r"(a[2]), "r"(a[3]), "r"(b0), "r"(b1));
}
__device__ __forceinline__ float siluf(float v) { return v / (1.f + __expf(-v)); }

// ---------------- gating + rmsnorm stats (one warp per token) ----------------
__global__ void __launch_bounds__(256) gate_kernel(const float* __restrict__ x,
                                                   const float* __restrict__ gw) {
    const int wid = threadIdx.x >> 5, lane = threadIdx.x & 31;
    const int t = blockIdx.x * 8 + wid;
    float xr[32];
    float ss = 0.f;
    const float* xp = x + (size_t)t * D_DIM + lane;
#pragma unroll
    for (int i = 0; i < 32; ++i) { xr[i] = xp[i * 32]; ss += xr[i] * xr[i]; }
    float sc[8];
#pragma unroll
    for (int e = 0; e < 8; ++e) {
        const float* gp = gw + e * D_DIM + lane;
        float s = 0.f;
#pragma unroll
        for (int i = 0; i < 32; ++i) s += xr[i] * gp[i * 32];
        sc[e] = s;
    }
#pragma unroll
    for (int o = 16; o > 0; o >>= 1) {
        ss += __shfl_xor_sync(0xffffffffu, ss, o);
#pragma unroll
        for (int e = 0; e < 8; ++e) sc[e] += __shfl_xor_sync(0xffffffffu, sc[e], o);
    }
    if (lane == 0) {
        g_inv[t] = rsqrtf(ss * (1.f / D_DIM) + 1e-6f);
        int i0 = 0; float v0 = sc[0];
#pragma unroll
        for (int e = 1; e < 8; ++e) if (sc[e] > v0) { v0 = sc[e]; i0 = e; }
        int i1 = (i0 == 0) ? 1 : 0; float v1 = sc[i1];
#pragma unroll
        for (int e = 0; e < 8; ++e)
            if (e != i0 && sc[e] > v1) { v1 = sc[e]; i1 = e; }
        const float e1 = __expf(v1 - v0);
        const float z  = 1.f + e1;
        g_tokE[2 * t] = i0; g_tokE[2 * t + 1] = i1;
        g_gw[2 * t] = 1.f / z; g_gw[2 * t + 1] = e1 / z;
        atomicAdd(&g_cnt[i0], 1);
        atomicAdd(&g_cnt[i1], 1);
    }
}

// ---------------- scan + scatter (single block) ----------------
__global__ void __launch_bounds__(1024) scan_scatter_kernel() {
    __shared__ int s_cur[E_EXP];
    const int tid = threadIdx.x;
    if (tid == 0) {
        int s = 0;
        for (int e = 0; e < E_EXP; ++e) { g_off[e] = s; s_cur[e] = s; s += g_cnt[e]; }
    }
    __syncthreads();
    for (int t = tid; t < T_TOK; t += 1024) {
#pragma unroll
        for (int k = 0; k < 2; ++k) {
            int e = g_tokE[2 * t + k];
            int s = atomicAdd(&s_cur[e], 1);
            g_perm[s] = t;
            g_slotE[s] = e;
            g_slot[2 * t + k] = s;
        }
    }
}

// ---------------- per-slot A prep: xa = bf16(x * inv_rms * ln_w[e]) ----------------
__global__ void __launch_bounds__(256) prep_a_kernel(const float* __restrict__ x,
                                                     const float* __restrict__ ln) {
    const int s = blockIdx.x;
    const int t = g_perm[s];
    const int e = g_slotE[s];
    const float inv = g_inv[t];
    const int d = threadIdx.x * 4;
    float4 xv = *reinterpret_cast<const float4*>(x + (size_t)t * D_DIM + d);
    float4 lv = *reinterpret_cast<const float4*>(ln + (size_t)e * D_DIM + d);
    __nv_bfloat162 lo = __floats2bfloat162_rn(xv.x * inv * lv.x, xv.y * inv * lv.y);
    __nv_bfloat162 hi = __floats2bfloat162_rn(xv.z * inv * lv.z, xv.w * inv * lv.w);
    uint2 u;
    u.x = *reinterpret_cast<uint32_t*>(&lo);
    u.y = *reinterpret_cast<uint32_t*>(&hi);
    *reinterpret_cast<uint2*>(g_xa + (size_t)s * D_DIM + d) = u;
}

// ================= GEMM settings (R7-proven) =================
#define KSTAGE 64
#define NBUF   3
#define G_STAGE 32768
#define G_SMEM  (NBUF * G_STAGE)
#define CONV_BLOCKS 8192               // 4096 w1/w3 + 4096 w2
#define GEMM1_BLOCKS (64 * 32 * 8)     // ntile x mtile x expert

// ---------------- FUSED: weight conversion + GEMM1 ----------------
// Blocks [0, 4096):   convert w1/w3, expert-major, flag[e] released after 512 chunks.
// Blocks [4096, 8192): convert w2 (consumed only by gemm2 — next kernel — always ready).
// Blocks [8192, ...):  gemm1 CTAs (expert ascending) spin-wait on flag[e].
__global__ void __launch_bounds__(256, 2) fused_conv_gemm1(const float* __restrict__ w1,
                                                           const float* __restrict__ w3,
                                                           const float* __restrict__ w2) {
    extern __shared__ __align__(128) char smem[];
    const int bid = blockIdx.x;
    const int tid = threadIdx.x;

    if (bid < CONV_BLOCKS) {
        const int which = bid >> 12;            // 0: w1/w3, 1: w2
        const int sub = bid & 4095;
        const int e = sub >> 9;
        const int chunk = sub & 511;
        const size_t base = ((size_t)e << 22) + ((size_t)chunk << 13);  // e*F*D + chunk*8192
        const int t4 = tid * 4;
        if (which == 0) {
#pragma unroll
            for (int i = 0; i < 8; ++i) {
                size_t idx = base + (size_t)i * 1024 + t4;
                float4 a = __ldg(reinterpret_cast<const float4*>(w1 + idx));
                float4 b = __ldg(reinterpret_cast<const float4*>(w3 + idx));
                __nv_bfloat162 a0 = __floats2bfloat162_rn(a.x, a.y);
                __nv_bfloat162 a1 = __floats2bfloat162_rn(a.z, a.w);
                __nv_bfloat162 b0 = __floats2bfloat162_rn(b.x, b.y);
                __nv_bfloat162 b1 = __floats2bfloat162_rn(b.z, b.w);
                uint2 ua, ub;
                ua.x = *reinterpret_cast<uint32_t*>(&a0); ua.y = *reinterpret_cast<uint32_t*>(&a1);
                ub.x = *reinterpret_cast<uint32_t*>(&b0); ub.y = *reinterpret_cast<uint32_t*>(&b1);
                *reinterpret_cast<uint2*>(g_w1b + idx) = ua;
                *reinterpret_cast<uint2*>(g_w3b + idx) = ub;
            }
            __threadfence();
            __syncthreads();
            if (tid == 0) {
                if (atomicAdd(&g_cdone[e], 1) == 511) {
                    __threadfence();
                    atomicExch(&g_flag[e], 1);
                }
            }
        } else {
#pragma unroll
            for (int i = 0; i < 8; ++i) {
                size_t idx = base + (size_t)i * 1024 + t4;
                float4 a = __ldg(reinterpret_cast<const float4*>(w2 + idx));
                __nv_bfloat162 a0 = __floats2bfloat162_rn(a.x, a.y);
                __nv_bfloat162 a1 = __floats2bfloat162_rn(a.z, a.w);
                uint2 ua;
                ua.x = *reinterpret_cast<uint32_t*>(&a0); ua.y = *reinterpret_cast<uint32_t*>(&a1);
                *reinterpret_cast<uint2*>(g_w2b + idx) = ua;
            }
        }
        return;
    }

    // ---- gemm1 role ----
    const int g = bid - CONV_BLOCKS;
    const int e = g >> 11;                      // 2048 tiles per expert (64 ntile x 32 mtile)
    const int rem = g & 2047;
    const int mtile = rem >> 6;
    const int ntile = rem & 63;
    const int cnt = g_cnt[e];
    if (mtile * 128 >= cnt) return;
    const int off = g_off[e];
    const int lane = tid & 31;
    const int w = tid >> 5;
    const int wm = w & 3, wn = w >> 2;

    // wait for this expert's weights (tid 0 spins; syncthreads propagates acquire)
    if (tid == 0) {
        uint32_t f;
        do {
            asm volatile("ld.acquire.gpu.global.u32 %0, [%1];" : "=r"(f) : "l"(&g_flag[e]) : "memory");
            if (!f) __nanosleep(128);
        } while (!f);
    }
    __syncthreads();

    const uint32_t sb = (uint32_t)__cvta_generic_to_shared(smem);

    const int mrow0 = off + mtile * 128;
    const int mlast = off + cnt - 1;

    const __nv_bfloat16* w1p = g_w1b + ((size_t)e * F_DIM + (size_t)ntile * 64) * D_DIM;
    const __nv_bfloat16* w3p = g_w3b + ((size_t)e * F_DIM + (size_t)ntile * 64) * D_DIM;

    const int rr = tid >> 3;
    const int cc = tid & 7;
    const uint32_t swoff = (uint32_t)cc << 4;

    auto load_stage = [&](int buf, int kt) {
        const uint32_t base = sb + (uint32_t)buf * G_STAGE;
        const int k0 = kt * KSTAGE;
#pragma unroll
        for (int p = 0; p < 4; ++p) {            // A: 128 rows (contiguous slots, clamped)
            int r = p * 32 + rr;
            int row = mrow0 + r; if (row > mlast) row = mlast;
            uint32_t so = (uint32_t)(r << 7) + (swoff ^ ((uint32_t)(r & 7) << 4));
            cp16s(base + so, g_xa + (size_t)row * D_DIM + k0 + cc * 8);
        }
#pragma unroll
        for (int p = 0; p < 2; ++p) {            // B1, B3: 64 rows each
            int r = p * 32 + rr;
            uint32_t so = (uint32_t)(r << 7) + (swoff ^ ((uint32_t)(r & 7) << 4));
            cp16s(base + 16384 + so, w1p + (size_t)r * D_DIM + k0 + cc * 8);
            cp16s(base + 24576 + so, w3p + (size_t)r * D_DIM + k0 + cc * 8);
        }
        cp_commit();
    };

    float acc1[2][4][4], acc3[2][4][4];
#pragma unroll
    for (int a = 0; a < 2; ++a)
#pragma unroll
        for (int b = 0; b < 4; ++b)
#pragma unroll
            for (int c = 0; c < 4; ++c) { acc1[a][b][c] = 0.f; acc3[a][b][c] = 0.f; }

    const int sx  = lane & 7;
    const int hiA = lane >> 4;
    const int rA  = wm * 32 + (lane & 15);
    const int hiB = (lane >> 3) & 1;
    const int rB  = wn * 32 + ((lane >> 4) & 1) * 8 + (lane & 7);
    const uint32_t aRow0 = (uint32_t)(rA << 7), aRow1 = (uint32_t)((rA + 16) << 7);
    const uint32_t bRow0 = (uint32_t)(rB << 7), bRow1 = (uint32_t)((rB + 16) << 7);

    auto compute_stage = [&](int buf) {
        const uint32_t base = sb + (uint32_t)buf * G_STAGE;
        const uint32_t Ab = base, B1b = base + 16384, B3b = base + 24576;
#pragma unroll
        for (int kk = 0; kk < 4; ++kk) {
            const uint32_t ao = (uint32_t)(((2 * kk + hiA) ^ sx) << 4);
            const uint32_t bo = (uint32_t)(((2 * kk + hiB) ^ sx) << 4);
            uint32_t a[2][4];
            ldsm4(a[0], Ab + aRow0 + ao);
            ldsm4(a[1], Ab + aRow1 + ao);
            uint32_t b1f[2][4], b3f[2][4];
            ldsm4(b1f[0], B1b + bRow0 + bo);
            ldsm4(b1f[1], B1b + bRow1 + bo);
            ldsm4(b3f[0], B3b + bRow0 + bo);
            ldsm4(b3f[1], B3b + bRow1 + bo);
#pragma unroll
            for (int im = 0; im < 2; ++im)
#pragma unroll
                for (int j = 0; j < 4; ++j) {
                    mma16816(acc1[im][j], a[im],
                             b1f[j >> 1][(j & 1) * 2], b1f[j >> 1][(j & 1) * 2 + 1]);
                    mma16816(acc3[im][j], a[im],
                             b3f[j >> 1][(j & 1) * 2], b3f[j >> 1][(j & 1) * 2 + 1]);
                }
        }
    };

    const int NK = D_DIM / KSTAGE;   // 16
    load_stage(0, 0);
    load_stage(1, 1);
    int bc = 0, bl = 2;
#pragma unroll 1
    for (int kt = 0; kt < NK; ++kt) {
        if (kt < NK - 1) cp_wait<1>();
        else             cp_wait<0>();
        __syncthreads();
        if (kt + 2 < NK) {
            load_stage(bl, kt + 2);
            bl = (bl == 2) ? 0 : bl + 1;
        }
        compute_stage(bc);
        bc = (bc == 2) ? 0 : bc + 1;
    }

    const int mbase = mtile * 128 + wm * 32 + (lane >> 2);
    const int fbase = ntile * 64 + wn * 32 + (lane & 3) * 2;
#pragma unroll
    for (int im = 0; im < 2; ++im)
#pragma unroll
        for (int j = 0; j < 4; ++j)
#pragma unroll
            for (int hh = 0; hh < 2; ++hh) {
                int m = mbase + im * 16 + hh * 8;
                if (m < cnt) {
                    float v0 = siluf(acc1[im][j][hh * 2])     * acc3[im][j][hh * 2];
                    float v1 = siluf(acc1[im][j][hh * 2 + 1]) * acc3[im][j][hh * 2 + 1];
                    *reinterpret_cast<__nv_bfloat162*>(
                        &g_h[(size_t)(off + m) * F_DIM + fbase + j * 8]) =
                        __floats2bfloat162_rn(v0, v1);
                }
            }
}

// ---------------- GEMM2 (h @ w2^T -> ys) ----------------
// CTA M=128, N=128 (warp 32x64, 4m x 2n). Experts reversed (g_h L2-hot).
__global__ void __launch_bounds__(256, 2) gemm2_kernel() {
    extern __shared__ __align__(128) char smem[];
    const int e = E_EXP - 1 - blockIdx.z;
    const int cnt = g_cnt[e];
    const int mtile = blockIdx.y;
    if (mtile * 128 >= cnt) return;
    const int ntile = blockIdx.x;     // 0..7
    const int off = g_off[e];
    const int tid = threadIdx.x;
    const int lane = tid & 31;
    const int w = tid >> 5;
    const int wm = w & 3, wn = w >> 2;

    const uint32_t sb = (uint32_t)__cvta_generic_to_shared(smem);
    const int mrow0 = off + mtile * 128;
    const int mlast = off + cnt - 1;

    const __nv_bfloat16* w2p = g_w2b + ((size_t)e * D_DIM + (size_t)ntile * 128) * F_DIM;

    const int rr = tid >> 3;
    const int cc = tid & 7;
    const uint32_t swoff = (uint32_t)cc << 4;

    auto load_stage = [&](int buf, int kt) {
        const uint32_t base = sb + (uint32_t)buf * G_STAGE;
        const int k0 = kt * KSTAGE;
#pragma unroll
        for (int p = 0; p < 4; ++p) {            // A: 128 rows of h
            int r = p * 32 + rr;
            int row = mrow0 + r; if (row > mlast) row = mlast;
            uint32_t so = (uint32_t)(r << 7) + (swoff ^ ((uint32_t)(r & 7) << 4));
            cp16s(base + so, g_h + (size_t)row * F_DIM + k0 + cc * 8);
        }
#pragma unroll
        for (int p = 0; p < 4; ++p) {            // B: 128 rows of w2
            int r = p * 32 + rr;
            uint32_t so = (uint32_t)(r << 7) + (swoff ^ ((uint32_t)(r & 7) << 4));
            cp16s(base + 16384 + so, w2p + (size_t)r * F_DIM + k0 + cc * 8);
        }
        cp_commit();
    };

    float acc[2][8][4];
#pragma unroll
    for (int a = 0; a < 2; ++a)
#pragma unroll
        for (int b = 0; b < 8; ++b)
#pragma unroll
            for (int c = 0; c < 4; ++c) acc[a][b][c] = 0.f;

    const int sx  = lane & 7;
    const int hiA = lane >> 4;
    const int rA  = wm * 32 + (lane & 15);
    const int hiB = (lane >> 3) & 1;
    const int rB  = wn * 64 + ((lane >> 4) & 1) * 8 + (lane & 7);
    const uint32_t aRow0 = (uint32_t)(rA << 7), aRow1 = (uint32_t)((rA + 16) << 7);
    uint32_t bRow[4];
#pragma unroll
    for (int i = 0; i < 4; ++i) bRow[i] = (uint32_t)((rB + i * 16) << 7);

    auto compute_stage = [&](int buf) {
        const uint32_t base = sb + (uint32_t)buf * G_STAGE;
        const uint32_t Ab = base, Bb = base + 16384;
#pragma unroll
        for (int kk = 0; kk < 4; ++kk) {
            const uint32_t ao = (uint32_t)(((2 * kk + hiA) ^ sx) << 4);
            const uint32_t bo = (uint32_t)(((2 * kk + hiB) ^ sx) << 4);
            uint32_t a[2][4];
            ldsm4(a[0], Ab + aRow0 + ao);
            ldsm4(a[1], Ab + aRow1 + ao);
            uint32_t bf[4][4];
#pragma unroll
            for (int i16 = 0; i16 < 4; ++i16)
                ldsm4(bf[i16], Bb + bRow[i16] + bo);
#pragma unroll
            for (int im = 0; im < 2; ++im)
#pragma unroll
                for (int j = 0; j < 8; ++j)
                    mma16816(acc[im][j], a[im],
                             bf[j >> 1][(j & 1) * 2], bf[j >> 1][(j & 1) * 2 + 1]);
        }
    };

    const int NK = F_DIM / KSTAGE;   // 64
    load_stage(0, 0);
    load_stage(1, 1);
    int bc = 0, bl = 2;
#pragma unroll 1
    for (int kt = 0; kt < NK; ++kt) {
        if (kt < NK - 1) cp_wait<1>();
        else             cp_wait<0>();
        __syncthreads();
        if (kt + 2 < NK) {
            load_stage(bl, kt + 2);
            bl = (bl == 2) ? 0 : bl + 1;
        }
        compute_stage(bc);
        bc = (bc == 2) ? 0 : bc + 1;
    }

    const int mbase = mtile * 128 + wm * 32 + (lane >> 2);
    const int dbase = ntile * 128 + wn * 64 + (lane & 3) * 2;
#pragma unroll
    for (int im = 0; im < 2; ++im)
#pragma unroll
        for (int j = 0; j < 8; ++j)
#pragma unroll
            for (int hh = 0; hh < 2; ++hh) {
                int m = mbase + im * 16 + hh * 8;
                if (m < cnt) {
                    float2 v;
                    v.x = acc[im][j][hh * 2];
                    v.y = acc[im][j][hh * 2 + 1];
                    *reinterpret_cast<float2*>(
                        &g_ys[(size_t)(off + m) * D_DIM + dbase + j * 8]) = v;
                }
            }
}

// ---------------- combine (residual + weighted) + reset counters/flags ----------------
__global__ void __launch_bounds__(256) combine_kernel(const float* __restrict__ x,
                                                      float* __restrict__ out) {
    const int t = blockIdx.x;
    if (blockIdx.x == 0 && threadIdx.x < E_EXP) {
        g_cnt[threadIdx.x] = 0;
        g_cdone[threadIdx.x] = 0;
        g_flag[threadIdx.x] = 0;
    }
    const int s0 = g_slot[2 * t], s1 = g_slot[2 * t + 1];
    const float g0 = g_gw[2 * t], g1 = g_gw[2 * t + 1];
    const int d = threadIdx.x * 4;
    float4 xv = *reinterpret_cast<const float4*>(x + (size_t)t * D_DIM + d);
    float4 y0 = *reinterpret_cast<const float4*>(g_ys + (size_t)s0 * D_DIM + d);
    float4 y1 = *reinterpret_cast<const float4*>(g_ys + (size_t)s1 * D_DIM + d);
    float4 o;
    o.x = xv.x + g0 * y0.x + g1 * y1.x;
    o.y = xv.y + g0 * y0.y + g1 * y1.y;
    o.z = xv.z + g0 * y0.z + g1 * y1.z;
    o.w = xv.w + g0 * y0.w + g1 * y1.w;
    *reinterpret_cast<float4*>(out + (size_t)t * D_DIM + d) = o;
}

// ---------------- launch (linear, single stream) ----------------
extern "C" void kernel_launch(void* const* d_in, const int* in_sizes, int n_in,
                              void* d_out, int out_size) {
    (void)in_sizes; (void)n_in; (void)out_size;
    const float* x      = (const float*)d_in[0];
    const float* gate_w = (const float*)d_in[1];
    const float* ln_w   = (const float*)d_in[2];
    const float* w1     = (const float*)d_in[3];
    const float* w3     = (const float*)d_in[4];
    const float* w2     = (const float*)d_in[5];
    float* out = (float*)d_out;

    cudaFuncSetAttribute(fused_conv_gemm1, cudaFuncAttributeMaxDynamicSharedMemorySize, G_SMEM);
    cudaFuncSetAttribute(gemm2_kernel, cudaFuncAttributeMaxDynamicSharedMemorySize, G_SMEM);

    gate_kernel<<<T_TOK / 8, 256>>>(x, gate_w);                                   // 0
    scan_scatter_kernel<<<1, 1024>>>();                                           // 1
    prep_a_kernel<<<NSLOT, 256>>>(x, ln_w);                                       // 2
    fused_conv_gemm1<<<CONV_BLOCKS + GEMM1_BLOCKS, 256, G_SMEM>>>(w1, w3, w2);    // 3
    gemm2_kernel<<<dim3(D_DIM / 128, T_TOK / 128, E_EXP), 256, G_SMEM>>>();       // 4
    combine_kernel<<<T_TOK, 256>>>(x, out);                                       // 5
}

// round 15
// speedup vs baseline: 1.4818x; 1.4818x over previous
#include <cuda_runtime.h>
#include <cuda_bf16.h>
#include <stdint.h>

#define E_EXP 8
#define D_DIM 1024
#define F_DIM 4096
#define T_TOK 4096
#define NSLOT (T_TOK * 2)

// ---------------- scratch (static __device__ arrays; no allocation) ----------------
__device__ __nv_bfloat16 g_xnb[(size_t)T_TOK * D_DIM];          // normalized x, bf16
__device__ __nv_bfloat16 g_w1b[(size_t)E_EXP * F_DIM * D_DIM];  // bf16(w1 * ln_w)
__device__ __nv_bfloat16 g_w3b[(size_t)E_EXP * F_DIM * D_DIM];  // bf16(w3 * ln_w)
__device__ __nv_bfloat16 g_w2b[(size_t)E_EXP * D_DIM * F_DIM];  // bf16(w2)
__device__ __nv_bfloat16 g_h[(size_t)NSLOT * F_DIM];            // gated activations
__device__ float         g_ys[(size_t)NSLOT * D_DIM];           // per-slot FFN output
__device__ int   g_cnt[E_EXP];     // zero at load; re-zeroed by combine each call
__device__ int   g_off[E_EXP];
__device__ int   g_perm[NSLOT];
__device__ int   g_tokE[NSLOT];
__device__ int   g_slot[NSLOT];
__device__ float g_gw[NSLOT];

// ---------------- small helpers ----------------
__device__ __forceinline__ void cp16s(uint32_t dst, const void* src) {
    asm volatile("cp.async.cg.shared.global [%0], [%1], 16;\n" :: "r"(dst), "l"(src));
}
__device__ __forceinline__ void cp_commit() { asm volatile("cp.async.commit_group;\n" ::: "memory"); }
template <int N>
__device__ __forceinline__ void cp_wait() { asm volatile("cp.async.wait_group %0;\n" :: "n"(N) : "memory"); }

__device__ __forceinline__ void ldsm4(uint32_t* r, uint32_t a) {
    asm volatile("ldmatrix.sync.aligned.m8n8.x4.shared.b16 {%0,%1,%2,%3}, [%4];\n"
                 : "=r"(r[0]), "=r"(r[1]), "=r"(r[2]), "=r"(r[3]) : "r"(a));
}
__device__ __forceinline__ void mma16816(float* c, const uint32_t* a, uint32_t b0, uint32_t b1) {
    asm volatile(
        "mma.sync.aligned.m16n8k16.row.col.f32.bf16.bf16.f32 "
        "{%0,%1,%2,%3}, {%4,%5,%6,%7}, {%8,%9}, {%0,%1,%2,%3};\n"
        : "+f"(c[0]), "+f"(c[1]), "+f"(c[2]), "+f"(c[3])
        : "r"(a[0]), "r"(a[1]), "r"(a[2]), "r"(a[3]), "r"(b0), "r"(b1));
}
__device__ __forceinline__ float siluf(float v) { return v / (1.f + __expf(-v)); }

// ---------------- gating + rmsnorm (one warp per token; gate_w staged in smem) ----------------
__global__ void __launch_bounds__(256) gate_kernel(const float* __restrict__ x,
                                                   const float* __restrict__ gw) {
    __shared__ float s_gw[E_EXP * D_DIM];       // 32 KB
    const int tid = threadIdx.x;
    const int wid = tid >> 5, lane = tid & 31;
    // stage gate_w once per block (coalesced float4)
#pragma unroll
    for (int i = 0; i < 8; ++i) {
        int idx = (i * 256 + tid) * 4;
        *reinterpret_cast<float4*>(s_gw + idx) =
            *reinterpret_cast<const float4*>(gw + idx);
    }
    __syncthreads();

    const int t = blockIdx.x * 8 + wid;
    float xr[32];
    float ss = 0.f;
    const float* xp = x + (size_t)t * D_DIM + lane;
#pragma unroll
    for (int i = 0; i < 32; ++i) { xr[i] = xp[i * 32]; ss += xr[i] * xr[i]; }
    float sc[8];
#pragma unroll
    for (int e = 0; e < 8; ++e) {
        const float* gp = s_gw + e * D_DIM + lane;
        float s = 0.f;
#pragma unroll
        for (int i = 0; i < 32; ++i) s += xr[i] * gp[i * 32];
        sc[e] = s;
    }
#pragma unroll
    for (int o = 16; o > 0; o >>= 1) {
        ss += __shfl_xor_sync(0xffffffffu, ss, o);
#pragma unroll
        for (int e = 0; e < 8; ++e) sc[e] += __shfl_xor_sync(0xffffffffu, sc[e], o);
    }
    const float inv = rsqrtf(ss * (1.f / D_DIM) + 1e-6f);
    __nv_bfloat16* xo = g_xnb + (size_t)t * D_DIM + lane;
#pragma unroll
    for (int i = 0; i < 32; ++i) xo[i * 32] = __float2bfloat16(xr[i] * inv);

    if (lane == 0) {
        int i0 = 0; float v0 = sc[0];
#pragma unroll
        for (int e = 1; e < 8; ++e) if (sc[e] > v0) { v0 = sc[e]; i0 = e; }
        int i1 = (i0 == 0) ? 1 : 0; float v1 = sc[i1];
#pragma unroll
        for (int e = 0; e < 8; ++e)
            if (e != i0 && sc[e] > v1) { v1 = sc[e]; i1 = e; }
        const float e1 = __expf(v1 - v0);
        const float z  = 1.f + e1;
        g_tokE[2 * t] = i0; g_tokE[2 * t + 1] = i1;
        g_gw[2 * t] = 1.f / z; g_gw[2 * t + 1] = e1 / z;
        atomicAdd(&g_cnt[i0], 1);
        atomicAdd(&g_cnt[i1], 1);
    }
}

// ---------------- scan + scatter (single block) ----------------
__global__ void __launch_bounds__(1024) scan_scatter_kernel() {
    __shared__ int s_cur[E_EXP];
    const int tid = threadIdx.x;
    if (tid == 0) {
        int s = 0;
        for (int e = 0; e < E_EXP; ++e) { g_off[e] = s; s_cur[e] = s; s += g_cnt[e]; }
    }
    __syncthreads();
    for (int t = tid; t < T_TOK; t += 1024) {
#pragma unroll
        for (int k = 0; k < 2; ++k) {
            int e = g_tokE[2 * t + k];
            int s = atomicAdd(&s_cur[e], 1);
            g_perm[s] = t;
            g_slot[2 * t + k] = s;
        }
    }
}

// ---------------- weight conversion fp32 -> bf16 (fold ln into w1/w3) ----------------
// Blocks iterate in REVERSE so expert 0 (first consumed by gemm1) is converted last (L2-hot).
__global__ void __launch_bounds__(256) conv_all_kernel(const float* __restrict__ w1,
                                                       const float* __restrict__ w3,
                                                       const float* __restrict__ w2,
                                                       const float* __restrict__ ln) {
    size_t i = ((size_t)(gridDim.x - 1 - blockIdx.x) * 256 + threadIdx.x) * 4;
    if (blockIdx.y == 0) {
        int e = (int)(i >> 22);          // F*D = 2^22
        int d = (int)(i & (D_DIM - 1));
        float4 l = *reinterpret_cast<const float4*>(ln + (size_t)e * D_DIM + d);
        float4 a = *reinterpret_cast<const float4*>(w1 + i);
        float4 b = *reinterpret_cast<const float4*>(w3 + i);
        __nv_bfloat162* o1 = reinterpret_cast<__nv_bfloat162*>(g_w1b + i);
        __nv_bfloat162* o3 = reinterpret_cast<__nv_bfloat162*>(g_w3b + i);
        o1[0] = __floats2bfloat162_rn(a.x * l.x, a.y * l.y);
        o1[1] = __floats2bfloat162_rn(a.z * l.z, a.w * l.w);
        o3[0] = __floats2bfloat162_rn(b.x * l.x, b.y * l.y);
        o3[1] = __floats2bfloat162_rn(b.z * l.z, b.w * l.w);
    } else {
        float4 a = *reinterpret_cast<const float4*>(w2 + i);
        __nv_bfloat162* o = reinterpret_cast<__nv_bfloat162*>(g_w2b + i);
        o[0] = __floats2bfloat162_rn(a.x, a.y);
        o[1] = __floats2bfloat162_rn(a.z, a.w);
    }
}

// ================= GEMM settings (R8-proven: KSTAGE=64, NBUF=3, 2 CTAs/SM) =================
#define KSTAGE 64
#define NBUF   3
#define G_STAGE 32768
#define G_SMEM  (1024 + NBUF * G_STAGE)

// ---------------- GEMM1 (xn @ w1^T, xn @ w3^T, fused silu-gate) ----------------
// CTA tile: M=128, N=64 per matrix. 8 warps (4m x 2n), warp tile 32x32 per matrix.
__global__ void __launch_bounds__(256, 2) gemm1_kernel() {
    extern __shared__ __align__(128) char smem[];
    const int e = blockIdx.z;
    const int cnt = g_cnt[e];
    const int mtile = blockIdx.y;
    if (mtile * 128 >= cnt) return;
    const int ntile = blockIdx.x;
    const int off = g_off[e];
    const int tid = threadIdx.x;
    const int lane = tid & 31;
    const int w = tid >> 5;
    const int wm = w & 3, wn = w >> 2;

    int* rows = (int*)smem;
    const uint32_t sb = (uint32_t)__cvta_generic_to_shared(smem);
    const uint32_t dataB = sb + 1024;

    if (tid < 128) {
        int m = mtile * 128 + tid;
        rows[tid] = g_perm[off + (m < cnt ? m : cnt - 1)];
    }
    __syncthreads();

    const __nv_bfloat16* w1p = g_w1b + ((size_t)e * F_DIM + (size_t)ntile * 64) * D_DIM;
    const __nv_bfloat16* w3p = g_w3b + ((size_t)e * F_DIM + (size_t)ntile * 64) * D_DIM;

    const int rr = tid >> 3;
    const int cc = tid & 7;
    const uint32_t swoff = (uint32_t)cc << 4;

    auto load_stage = [&](int buf, int kt) {
        const uint32_t base = dataB + (uint32_t)buf * G_STAGE;
        const int k0 = kt * KSTAGE;
#pragma unroll
        for (int p = 0; p < 4; ++p) {            // A: 128 rows
            int r = p * 32 + rr;
            uint32_t so = (uint32_t)(r << 7) + (swoff ^ ((uint32_t)(r & 7) << 4));
            cp16s(base + so, g_xnb + (size_t)rows[r] * D_DIM + k0 + cc * 8);
        }
#pragma unroll
        for (int p = 0; p < 2; ++p) {            // B1, B3: 64 rows each
            int r = p * 32 + rr;
            uint32_t so = (uint32_t)(r << 7) + (swoff ^ ((uint32_t)(r & 7) << 4));
            cp16s(base + 16384 + so, w1p + (size_t)r * D_DIM + k0 + cc * 8);
            cp16s(base + 24576 + so, w3p + (size_t)r * D_DIM + k0 + cc * 8);
        }
        cp_commit();
    };

    float acc1[2][4][4], acc3[2][4][4];
#pragma unroll
    for (int a = 0; a < 2; ++a)
#pragma unroll
        for (int b = 0; b < 4; ++b)
#pragma unroll
            for (int c = 0; c < 4; ++c) { acc1[a][b][c] = 0.f; acc3[a][b][c] = 0.f; }

    const int sx  = lane & 7;
    const int hiA = lane >> 4;
    const int rA  = wm * 32 + (lane & 15);
    const int hiB = (lane >> 3) & 1;
    const int rB  = wn * 32 + ((lane >> 4) & 1) * 8 + (lane & 7);
    const uint32_t aRow0 = (uint32_t)(rA << 7), aRow1 = (uint32_t)((rA + 16) << 7);
    const uint32_t bRow0 = (uint32_t)(rB << 7), bRow1 = (uint32_t)((rB + 16) << 7);

    auto compute_stage = [&](int buf) {
        const uint32_t base = dataB + (uint32_t)buf * G_STAGE;
        const uint32_t Ab = base, B1b = base + 16384, B3b = base + 24576;
#pragma unroll
        for (int kk = 0; kk < 4; ++kk) {
            const uint32_t ao = (uint32_t)(((2 * kk + hiA) ^ sx) << 4);
            const uint32_t bo = (uint32_t)(((2 * kk + hiB) ^ sx) << 4);
            uint32_t a[2][4];
            ldsm4(a[0], Ab + aRow0 + ao);
            ldsm4(a[1], Ab + aRow1 + ao);
            uint32_t b1f[2][4], b3f[2][4];
            ldsm4(b1f[0], B1b + bRow0 + bo);
            ldsm4(b1f[1], B1b + bRow1 + bo);
            ldsm4(b3f[0], B3b + bRow0 + bo);
            ldsm4(b3f[1], B3b + bRow1 + bo);
#pragma unroll
            for (int im = 0; im < 2; ++im)
#pragma unroll
                for (int j = 0; j < 4; ++j) {
                    mma16816(acc1[im][j], a[im],
                             b1f[j >> 1][(j & 1) * 2], b1f[j >> 1][(j & 1) * 2 + 1]);
                    mma16816(acc3[im][j], a[im],
                             b3f[j >> 1][(j & 1) * 2], b3f[j >> 1][(j & 1) * 2 + 1]);
                }
        }
    };

    const int NK = D_DIM / KSTAGE;   // 16
    load_stage(0, 0);
    load_stage(1, 1);
    int bc = 0, bl = 2;
#pragma unroll 1
    for (int kt = 0; kt < NK; ++kt) {
        if (kt < NK - 1) cp_wait<1>();
        else             cp_wait<0>();
        __syncthreads();
        if (kt + 2 < NK) {
            load_stage(bl, kt + 2);
            bl = (bl == 2) ? 0 : bl + 1;
        }
        compute_stage(bc);
        bc = (bc == 2) ? 0 : bc + 1;
    }

    const int mbase = mtile * 128 + wm * 32 + (lane >> 2);
    const int fbase = ntile * 64 + wn * 32 + (lane & 3) * 2;
#pragma unroll
    for (int im = 0; im < 2; ++im)
#pragma unroll
        for (int j = 0; j < 4; ++j)
#pragma unroll
            for (int hh = 0; hh < 2; ++hh) {
                int m = mbase + im * 16 + hh * 8;
                if (m < cnt) {
                    float v0 = siluf(acc1[im][j][hh * 2])     * acc3[im][j][hh * 2];
                    float v1 = siluf(acc1[im][j][hh * 2 + 1]) * acc3[im][j][hh * 2 + 1];
                    *reinterpret_cast<__nv_bfloat162*>(
                        &g_h[(size_t)(off + m) * F_DIM + fbase + j * 8]) =
                        __floats2bfloat162_rn(v0, v1);
                }
            }
}

// ---------------- GEMM2 (h @ w2^T -> ys) ----------------
// CTA tile: M=128, N=128. 8 warps (4m x 2n), warp tile 32x64. Experts reversed.
__global__ void __launch_bounds__(256, 2) gemm2_kernel() {
    extern __shared__ __align__(128) char smem[];
    const int e = E_EXP - 1 - blockIdx.z;
    const int cnt = g_cnt[e];
    const int mtile = blockIdx.y;
    if (mtile * 128 >= cnt) return;
    const int ntile = blockIdx.x;     // 0..7
    const int off = g_off[e];
    const int tid = threadIdx.x;
    const int lane = tid & 31;
    const int w = tid >> 5;
    const int wm = w & 3, wn = w >> 2;

    int* rowsA = (int*)smem;
    const uint32_t sb = (uint32_t)__cvta_generic_to_shared(smem);
    const uint32_t dataB = sb + 1024;

    if (tid < 128) {
        int m = mtile * 128 + tid;
        rowsA[tid] = off + (m < cnt ? m : cnt - 1);
    }
    __syncthreads();

    const __nv_bfloat16* w2p = g_w2b + ((size_t)e * D_DIM + (size_t)ntile * 128) * F_DIM;

    const int rr = tid >> 3;
    const int cc = tid & 7;
    const uint32_t swoff = (uint32_t)cc << 4;

    auto load_stage = [&](int buf, int kt) {
        const uint32_t base = dataB + (uint32_t)buf * G_STAGE;
        const int k0 = kt * KSTAGE;
#pragma unroll
        for (int p = 0; p < 4; ++p) {            // A: 128 rows of h
            int r = p * 32 + rr;
            uint32_t so = (uint32_t)(r << 7) + (swoff ^ ((uint32_t)(r & 7) << 4));
            cp16s(base + so, g_h + (size_t)rowsA[r] * F_DIM + k0 + cc * 8);
        }
#pragma unroll
        for (int p = 0; p < 4; ++p) {            // B: 128 rows of w2
            int r = p * 32 + rr;
            uint32_t so = (uint32_t)(r << 7) + (swoff ^ ((uint32_t)(r & 7) << 4));
            cp16s(base + 16384 + so, w2p + (size_t)r * F_DIM + k0 + cc * 8);
        }
        cp_commit();
    };

    float acc[2][8][4];
#pragma unroll
    for (int a = 0; a < 2; ++a)
#pragma unroll
        for (int b = 0; b < 8; ++b)
#pragma unroll
            for (int c = 0; c < 4; ++c) acc[a][b][c] = 0.f;

    const int sx  = lane & 7;
    const int hiA = lane >> 4;
    const int rA  = wm * 32 + (lane & 15);
    const int hiB = (lane >> 3) & 1;
    const int rB  = wn * 64 + ((lane >> 4) & 1) * 8 + (lane & 7);
    const uint32_t aRow0 = (uint32_t)(rA << 7), aRow1 = (uint32_t)((rA + 16) << 7);
    uint32_t bRow[4];
#pragma unroll
    for (int i = 0; i < 4; ++i) bRow[i] = (uint32_t)((rB + i * 16) << 7);

    auto compute_stage = [&](int buf) {
        const uint32_t base = dataB + (uint32_t)buf * G_STAGE;
        const uint32_t Ab = base, Bb = base + 16384;
#pragma unroll
        for (int kk = 0; kk < 4; ++kk) {
            const uint32_t ao = (uint32_t)(((2 * kk + hiA) ^ sx) << 4);
            const uint32_t bo = (uint32_t)(((2 * kk + hiB) ^ sx) << 4);
            uint32_t a[2][4];
            ldsm4(a[0], Ab + aRow0 + ao);
            ldsm4(a[1], Ab + aRow1 + ao);
            uint32_t bf[4][4];
#pragma unroll
            for (int i16 = 0; i16 < 4; ++i16)
                ldsm4(bf[i16], Bb + bRow[i16] + bo);
#pragma unroll
            for (int im = 0; im < 2; ++im)
#pragma unroll
                for (int j = 0; j < 8; ++j)
                    mma16816(acc[im][j], a[im],
                             bf[j >> 1][(j & 1) * 2], bf[j >> 1][(j & 1) * 2 + 1]);
        }
    };

    const int NK = F_DIM / KSTAGE;   // 64
    load_stage(0, 0);
    load_stage(1, 1);
    int bc = 0, bl = 2;
#pragma unroll 1
    for (int kt = 0; kt < NK; ++kt) {
        if (kt < NK - 1) cp_wait<1>();
        else             cp_wait<0>();
        __syncthreads();
        if (kt + 2 < NK) {
            load_stage(bl, kt + 2);
            bl = (bl == 2) ? 0 : bl + 1;
        }
        compute_stage(bc);
        bc = (bc == 2) ? 0 : bc + 1;
    }

    const int mbase = mtile * 128 + wm * 32 + (lane >> 2);
    const int dbase = ntile * 128 + wn * 64 + (lane & 3) * 2;
#pragma unroll
    for (int im = 0; im < 2; ++im)
#pragma unroll
        for (int j = 0; j < 8; ++j)
#pragma unroll
            for (int hh = 0; hh < 2; ++hh) {
                int m = mbase + im * 16 + hh * 8;
                if (m < cnt) {
                    float2 v;
                    v.x = acc[im][j][hh * 2];
                    v.y = acc[im][j][hh * 2 + 1];
                    *reinterpret_cast<float2*>(
                        &g_ys[(size_t)(off + m) * D_DIM + dbase + j * 8]) = v;
                }
            }
}

// ---------------- combine (residual + weighted expert outputs) + counter reset ----
__global__ void __launch_bounds__(256) combine_kernel(const float* __restrict__ x,
                                                      float* __restrict__ out) {
    const int t = blockIdx.x;
    if (blockIdx.x == 0 && threadIdx.x < E_EXP) g_cnt[threadIdx.x] = 0;  // reset for next call
    const int s0 = g_slot[2 * t], s1 = g_slot[2 * t + 1];
    const float g0 = g_gw[2 * t], g1 = g_gw[2 * t + 1];
    const int d = threadIdx.x * 4;
    float4 xv = *reinterpret_cast<const float4*>(x + (size_t)t * D_DIM + d);
    float4 y0 = *reinterpret_cast<const float4*>(g_ys + (size_t)s0 * D_DIM + d);
    float4 y1 = *reinterpret_cast<const float4*>(g_ys + (size_t)s1 * D_DIM + d);
    float4 o;
    o.x = xv.x + g0 * y0.x + g1 * y1.x;
    o.y = xv.y + g0 * y0.y + g1 * y1.y;
    o.z = xv.z + g0 * y0.z + g1 * y1.z;
    o.w = xv.w + g0 * y0.w + g1 * y1.w;
    *reinterpret_cast<float4*>(out + (size_t)t * D_DIM + d) = o;
}

// ---------------- launch (linear, single stream) ----------------
extern "C" void kernel_launch(void* const* d_in, const int* in_sizes, int n_in,
                              void* d_out, int out_size) {
    (void)in_sizes; (void)n_in; (void)out_size;
    const float* x      = (const float*)d_in[0];
    const float* gate_w = (const float*)d_in[1];
    const float* ln_w   = (const float*)d_in[2];
    const float* w1     = (const float*)d_in[3];
    const float* w3     = (const float*)d_in[4];
    const float* w2     = (const float*)d_in[5];
    float* out = (float*)d_out;

    cudaFuncSetAttribute(gemm1_kernel, cudaFuncAttributeMaxDynamicSharedMemorySize, G_SMEM);
    cudaFuncSetAttribute(gemm2_kernel, cudaFuncAttributeMaxDynamicSharedMemorySize, G_SMEM);

    gate_kernel<<<T_TOK / 8, 256>>>(x, gate_w);                                   // 0
    scan_scatter_kernel<<<1, 1024>>>();                                           // 1
    conv_all_kernel<<<dim3((E_EXP * F_DIM * D_DIM) / 4 / 256, 2), 256>>>(w1, w3, w2, ln_w); // 2
    gemm1_kernel<<<dim3(F_DIM / 64, T_TOK / 128, E_EXP), 256, G_SMEM>>>();        // 3
    gemm2_kernel<<<dim3(D_DIM / 128, T_TOK / 128, E_EXP), 256, G_SMEM>>>();       // 4
    combine_kernel<<<T_TOK, 256>>>(x, out);                                       // 5
}

// round 16
// speedup vs baseline: 1.5258x; 1.0297x over previous
#include <cuda_runtime.h>
#include <cuda_bf16.h>
#include <stdint.h>

#define E_EXP 8
#define D_DIM 1024
#define F_DIM 4096
#define T_TOK 4096
#define NSLOT (T_TOK * 2)

// ---------------- scratch (static __device__ arrays; no allocation) ----------------
__device__ __nv_bfloat16 g_xnb[(size_t)T_TOK * D_DIM];          // normalized x, bf16
__device__ __nv_bfloat16 g_w1b[(size_t)E_EXP * F_DIM * D_DIM];  // bf16(w1 * ln_w)
__device__ __nv_bfloat16 g_w3b[(size_t)E_EXP * F_DIM * D_DIM];  // bf16(w3 * ln_w)
__device__ __nv_bfloat16 g_w2b[(size_t)E_EXP * D_DIM * F_DIM];  // bf16(w2)
__device__ __nv_bfloat16 g_h[(size_t)NSLOT * F_DIM];            // gated activations
__device__ float         g_ys[(size_t)NSLOT * D_DIM];           // per-slot FFN output
__device__ int   g_cnt[E_EXP];     // zero at load; re-zeroed by combine each call
__device__ int   g_off[E_EXP];
__device__ int   g_perm[NSLOT];
__device__ int   g_tokE[NSLOT];
__device__ int   g_slot[NSLOT];
__device__ float g_gw[NSLOT];

// ---------------- small helpers ----------------
__device__ __forceinline__ void cp16s(uint32_t dst, const void* src) {
    asm volatile("cp.async.cg.shared.global [%0], [%1], 16;\n" :: "r"(dst), "l"(src));
}
__device__ __forceinline__ void cp_commit() { asm volatile("cp.async.commit_group;\n" ::: "memory"); }
template <int N>
__device__ __forceinline__ void cp_wait() { asm volatile("cp.async.wait_group %0;\n" :: "n"(N) : "memory"); }

__device__ __forceinline__ void ldsm4(uint32_t* r, uint32_t a) {
    asm volatile("ldmatrix.sync.aligned.m8n8.x4.shared.b16 {%0,%1,%2,%3}, [%4];\n"
                 : "=r"(r[0]), "=r"(r[1]), "=r"(r[2]), "=r"(r[3]) : "r"(a));
}
__device__ __forceinline__ void mma16816(float* c, const uint32_t* a, uint32_t b0, uint32_t b1) {
    asm volatile(
        "mma.sync.aligned.m16n8k16.row.col.f32.bf16.bf16.f32 "
        "{%0,%1,%2,%3}, {%4,%5,%6,%7}, {%8,%9}, {%0,%1,%2,%3};\n"
        : "+f"(c[0]), "+f"(c[1]), "+f"(c[2]), "+f"(c[3])
        : "r"(a[0]), "r"(a[1]), "r"(a[2]), "r"(a[3]), "r"(b0), "r"(b1));
}
__device__ __forceinline__ float siluf(float v) { return v / (1.f + __expf(-v)); }

// ---------------- kernel 0: gating/rmsnorm (blocks 0..511) + conv13 (blocks 512..4607) ----
// conv13 output (g_w1b/g_w3b) is first read by the NEXT kernel launch that needs it
// (gemm1) — no intra-kernel dependency, pure grid packing.
#define GATE_BLOCKS 512
#define C13_BLOCKS  4096
__global__ void __launch_bounds__(256) gate_conv13_kernel(const float* __restrict__ x,
                                                          const float* __restrict__ gw,
                                                          const float* __restrict__ w1,
                                                          const float* __restrict__ w3,
                                                          const float* __restrict__ ln) {
    __shared__ float s_gw[E_EXP * D_DIM];       // 32 KB (gate path only)
    const int tid = threadIdx.x;

    if (blockIdx.x >= GATE_BLOCKS) {
        // ---- conv13 role: fold ln into w1/w3, fp32 -> bf16 ----
        // reversed so expert 0 (first consumed by gemm1) is converted last (L2-hot)
        const int sub = (C13_BLOCKS - 1) - (int)(blockIdx.x - GATE_BLOCKS);
        const int e = sub >> 9;
        const int chunk = sub & 511;
        const size_t base = ((size_t)e << 22) + ((size_t)chunk << 13);
        const int t4 = tid * 4;
#pragma unroll
        for (int i = 0; i < 8; ++i) {
            size_t idx = base + (size_t)i * 1024 + t4;
            int d = (int)(idx & (D_DIM - 1));
            float4 l = __ldg(reinterpret_cast<const float4*>(ln + (size_t)e * D_DIM + d));
            float4 a = __ldg(reinterpret_cast<const float4*>(w1 + idx));
            float4 b = __ldg(reinterpret_cast<const float4*>(w3 + idx));
            __nv_bfloat162 a0 = __floats2bfloat162_rn(a.x * l.x, a.y * l.y);
            __nv_bfloat162 a1 = __floats2bfloat162_rn(a.z * l.z, a.w * l.w);
            __nv_bfloat162 b0 = __floats2bfloat162_rn(b.x * l.x, b.y * l.y);
            __nv_bfloat162 b1 = __floats2bfloat162_rn(b.z * l.z, b.w * l.w);
            uint2 ua, ub;
            ua.x = *reinterpret_cast<uint32_t*>(&a0); ua.y = *reinterpret_cast<uint32_t*>(&a1);
            ub.x = *reinterpret_cast<uint32_t*>(&b0); ub.y = *reinterpret_cast<uint32_t*>(&b1);
            *reinterpret_cast<uint2*>(g_w1b + idx) = ua;
            *reinterpret_cast<uint2*>(g_w3b + idx) = ub;
        }
        return;
    }

    // ---- gate role ----
    const int wid = tid >> 5, lane = tid & 31;
#pragma unroll
    for (int i = 0; i < 8; ++i) {
        int idx = (i * 256 + tid) * 4;
        *reinterpret_cast<float4*>(s_gw + idx) =
            *reinterpret_cast<const float4*>(gw + idx);
    }
    __syncthreads();

    const int t = blockIdx.x * 8 + wid;
    float xr[32];
    float ss = 0.f;
    const float* xp = x + (size_t)t * D_DIM + lane;
#pragma unroll
    for (int i = 0; i < 32; ++i) { xr[i] = xp[i * 32]; ss += xr[i] * xr[i]; }
    float sc[8];
#pragma unroll
    for (int e = 0; e < 8; ++e) {
        const float* gp = s_gw + e * D_DIM + lane;
        float s = 0.f;
#pragma unroll
        for (int i = 0; i < 32; ++i) s += xr[i] * gp[i * 32];
        sc[e] = s;
    }
#pragma unroll
    for (int o = 16; o > 0; o >>= 1) {
        ss += __shfl_xor_sync(0xffffffffu, ss, o);
#pragma unroll
        for (int e = 0; e < 8; ++e) sc[e] += __shfl_xor_sync(0xffffffffu, sc[e], o);
    }
    const float inv = rsqrtf(ss * (1.f / D_DIM) + 1e-6f);
    __nv_bfloat16* xo = g_xnb + (size_t)t * D_DIM + lane;
#pragma unroll
    for (int i = 0; i < 32; ++i) xo[i * 32] = __float2bfloat16(xr[i] * inv);

    if (lane == 0) {
        int i0 = 0; float v0 = sc[0];
#pragma unroll
        for (int e = 1; e < 8; ++e) if (sc[e] > v0) { v0 = sc[e]; i0 = e; }
        int i1 = (i0 == 0) ? 1 : 0; float v1 = sc[i1];
#pragma unroll
        for (int e = 0; e < 8; ++e)
            if (e != i0 && sc[e] > v1) { v1 = sc[e]; i1 = e; }
        const float e1 = __expf(v1 - v0);
        const float z  = 1.f + e1;
        g_tokE[2 * t] = i0; g_tokE[2 * t + 1] = i1;
        g_gw[2 * t] = 1.f / z; g_gw[2 * t + 1] = e1 / z;
        atomicAdd(&g_cnt[i0], 1);
        atomicAdd(&g_cnt[i1], 1);
    }
}

// ---------------- scan + scatter (single block) ----------------
__global__ void __launch_bounds__(1024) scan_scatter_kernel() {
    __shared__ int s_cur[E_EXP];
    const int tid = threadIdx.x;
    if (tid == 0) {
        int s = 0;
        for (int e = 0; e < E_EXP; ++e) { g_off[e] = s; s_cur[e] = s; s += g_cnt[e]; }
    }
    __syncthreads();
    for (int t = tid; t < T_TOK; t += 1024) {
#pragma unroll
        for (int k = 0; k < 2; ++k) {
            int e = g_tokE[2 * t + k];
            int s = atomicAdd(&s_cur[e], 1);
            g_perm[s] = t;
            g_slot[2 * t + k] = s;
        }
    }
}

// ================= GEMM settings (R8-proven: KSTAGE=64, NBUF=3, 2 CTAs/SM) =================
#define KSTAGE 64
#define NBUF   3
#define G_STAGE 32768
#define G_SMEM  (1024 + NBUF * G_STAGE)
#define G1_TILES (64 * 32 * 8)     // ntile x mtile x expert = 16384
#define C2_BLOCKS 4096

// ---------------- kernel 2: GEMM1 tiles (blocks 0..16383) + conv2 (blocks 16384..20479) ----
// conv2 converts w2 (fp32->bf16) — consumed only by gemm2 (next kernel), so the
// conv blocks have NO dependency on anything in this kernel. They backfill the
// slack created by gemm1's interleaved empty tiles and low DRAM utilization.
__global__ void __launch_bounds__(256, 2) gemm1_kernel(const float* __restrict__ w2) {
    extern __shared__ __align__(128) char smem[];
    const int bid = blockIdx.x;
    const int tid = threadIdx.x;

    if (bid >= G1_TILES) {
        // ---- conv2 role: w2 fp32 -> bf16 (expert ascending: e7 converted last, L2-hot for gemm2) ----
        const int sub = bid - G1_TILES;
        const size_t base = (size_t)sub << 13;      // sub * 8192 elems
        const int t4 = tid * 4;
#pragma unroll
        for (int i = 0; i < 8; ++i) {
            size_t idx = base + (size_t)i * 1024 + t4;
            float4 a = __ldg(reinterpret_cast<const float4*>(w2 + idx));
            __nv_bfloat162 a0 = __floats2bfloat162_rn(a.x, a.y);
            __nv_bfloat162 a1 = __floats2bfloat162_rn(a.z, a.w);
            uint2 ua;
            ua.x = *reinterpret_cast<uint32_t*>(&a0); ua.y = *reinterpret_cast<uint32_t*>(&a1);
            *reinterpret_cast<uint2*>(g_w2b + idx) = ua;
        }
        return;
    }

    // ---- gemm1 tile role (identical math to R15) ----
    const int e = bid >> 11;                    // 2048 tiles/expert (32 mtile x 64 ntile)
    const int rem = bid & 2047;
    const int mtile = rem >> 6;
    const int ntile = rem & 63;
    const int cnt = g_cnt[e];
    if (mtile * 128 >= cnt) return;
    const int off = g_off[e];
    const int lane = tid & 31;
    const int w = tid >> 5;
    const int wm = w & 3, wn = w >> 2;

    int* rows = (int*)smem;
    const uint32_t sb = (uint32_t)__cvta_generic_to_shared(smem);
    const uint32_t dataB = sb + 1024;

    if (tid < 128) {
        int m = mtile * 128 + tid;
        rows[tid] = g_perm[off + (m < cnt ? m : cnt - 1)];
    }
    __syncthreads();

    const __nv_bfloat16* w1p = g_w1b + ((size_t)e * F_DIM + (size_t)ntile * 64) * D_DIM;
    const __nv_bfloat16* w3p = g_w3b + ((size_t)e * F_DIM + (size_t)ntile * 64) * D_DIM;

    const int rr = tid >> 3;
    const int cc = tid & 7;
    const uint32_t swoff = (uint32_t)cc << 4;

    auto load_stage = [&](int buf, int kt) {
        const uint32_t base = dataB + (uint32_t)buf * G_STAGE;
        const int k0 = kt * KSTAGE;
#pragma unroll
        for (int p = 0; p < 4; ++p) {            // A: 128 rows
            int r = p * 32 + rr;
            uint32_t so = (uint32_t)(r << 7) + (swoff ^ ((uint32_t)(r & 7) << 4));
            cp16s(base + so, g_xnb + (size_t)rows[r] * D_DIM + k0 + cc * 8);
        }
#pragma unroll
        for (int p = 0; p < 2; ++p) {            // B1, B3: 64 rows each
            int r = p * 32 + rr;
            uint32_t so = (uint32_t)(r << 7) + (swoff ^ ((uint32_t)(r & 7) << 4));
            cp16s(base + 16384 + so, w1p + (size_t)r * D_DIM + k0 + cc * 8);
            cp16s(base + 24576 + so, w3p + (size_t)r * D_DIM + k0 + cc * 8);
        }
        cp_commit();
    };

    float acc1[2][4][4], acc3[2][4][4];
#pragma unroll
    for (int a = 0; a < 2; ++a)
#pragma unroll
        for (int b = 0; b < 4; ++b)
#pragma unroll
            for (int c = 0; c < 4; ++c) { acc1[a][b][c] = 0.f; acc3[a][b][c] = 0.f; }

    const int sx  = lane & 7;
    const int hiA = lane >> 4;
    const int rA  = wm * 32 + (lane & 15);
    const int hiB = (lane >> 3) & 1;
    const int rB  = wn * 32 + ((lane >> 4) & 1) * 8 + (lane & 7);
    const uint32_t aRow0 = (uint32_t)(rA << 7), aRow1 = (uint32_t)((rA + 16) << 7);
    const uint32_t bRow0 = (uint32_t)(rB << 7), bRow1 = (uint32_t)((rB + 16) << 7);

    auto compute_stage = [&](int buf) {
        const uint32_t base = dataB + (uint32_t)buf * G_STAGE;
        const uint32_t Ab = base, B1b = base + 16384, B3b = base + 24576;
#pragma unroll
        for (int kk = 0; kk < 4; ++kk) {
            const uint32_t ao = (uint32_t)(((2 * kk + hiA) ^ sx) << 4);
            const uint32_t bo = (uint32_t)(((2 * kk + hiB) ^ sx) << 4);
            uint32_t a[2][4];
            ldsm4(a[0], Ab + aRow0 + ao);
            ldsm4(a[1], Ab + aRow1 + ao);
            uint32_t b1f[2][4], b3f[2][4];
            ldsm4(b1f[0], B1b + bRow0 + bo);
            ldsm4(b1f[1], B1b + bRow1 + bo);
            ldsm4(b3f[0], B3b + bRow0 + bo);
            ldsm4(b3f[1], B3b + bRow1 + bo);
#pragma unroll
            for (int im = 0; im < 2; ++im)
#pragma unroll
                for (int j = 0; j < 4; ++j) {
                    mma16816(acc1[im][j], a[im],
                             b1f[j >> 1][(j & 1) * 2], b1f[j >> 1][(j & 1) * 2 + 1]);
                    mma16816(acc3[im][j], a[im],
                             b3f[j >> 1][(j & 1) * 2], b3f[j >> 1][(j & 1) * 2 + 1]);
                }
        }
    };

    const int NK = D_DIM / KSTAGE;   // 16
    load_stage(0, 0);
    load_stage(1, 1);
    int bc = 0, bl = 2;
#pragma unroll 1
    for (int kt = 0; kt < NK; ++kt) {
        if (kt < NK - 1) cp_wait<1>();
        else             cp_wait<0>();
        __syncthreads();
        if (kt + 2 < NK) {
            load_stage(bl, kt + 2);
            bl = (bl == 2) ? 0 : bl + 1;
        }
        compute_stage(bc);
        bc = (bc == 2) ? 0 : bc + 1;
    }

    const int mbase = mtile * 128 + wm * 32 + (lane >> 2);
    const int fbase = ntile * 64 + wn * 32 + (lane & 3) * 2;
#pragma unroll
    for (int im = 0; im < 2; ++im)
#pragma unroll
        for (int j = 0; j < 4; ++j)
#pragma unroll
            for (int hh = 0; hh < 2; ++hh) {
                int m = mbase + im * 16 + hh * 8;
                if (m < cnt) {
                    float v0 = siluf(acc1[im][j][hh * 2])     * acc3[im][j][hh * 2];
                    float v1 = siluf(acc1[im][j][hh * 2 + 1]) * acc3[im][j][hh * 2 + 1];
                    *reinterpret_cast<__nv_bfloat162*>(
                        &g_h[(size_t)(off + m) * F_DIM + fbase + j * 8]) =
                        __floats2bfloat162_rn(v0, v1);
                }
            }
}

// ---------------- GEMM2 (h @ w2^T -> ys) ----------------
// CTA tile: M=128, N=128. 8 warps (4m x 2n), warp tile 32x64. Experts reversed.
__global__ void __launch_bounds__(256, 2) gemm2_kernel() {
    extern __shared__ __align__(128) char smem[];
    const int e = E_EXP - 1 - blockIdx.z;
    const int cnt = g_cnt[e];
    const int mtile = blockIdx.y;
    if (mtile * 128 >= cnt) return;
    const int ntile = blockIdx.x;     // 0..7
    const int off = g_off[e];
    const int tid = threadIdx.x;
    const int lane = tid & 31;
    const int w = tid >> 5;
    const int wm = w & 3, wn = w >> 2;

    int* rowsA = (int*)smem;
    const uint32_t sb = (uint32_t)__cvta_generic_to_shared(smem);
    const uint32_t dataB = sb + 1024;

    if (tid < 128) {
        int m = mtile * 128 + tid;
        rowsA[tid] = off + (m < cnt ? m : cnt - 1);
    }
    __syncthreads();

    const __nv_bfloat16* w2p = g_w2b + ((size_t)e * D_DIM + (size_t)ntile * 128) * F_DIM;

    const int rr = tid >> 3;
    const int cc = tid & 7;
    const uint32_t swoff = (uint32_t)cc << 4;

    auto load_stage = [&](int buf, int kt) {
        const uint32_t base = dataB + (uint32_t)buf * G_STAGE;
        const int k0 = kt * KSTAGE;
#pragma unroll
        for (int p = 0; p < 4; ++p) {            // A: 128 rows of h
            int r = p * 32 + rr;
            uint32_t so = (uint32_t)(r << 7) + (swoff ^ ((uint32_t)(r & 7) << 4));
            cp16s(base + so, g_h + (size_t)rowsA[r] * F_DIM + k0 + cc * 8);
        }
#pragma unroll
        for (int p = 0; p < 4; ++p) {            // B: 128 rows of w2
            int r = p * 32 + rr;
            uint32_t so = (uint32_t)(r << 7) + (swoff ^ ((uint32_t)(r & 7) << 4));
            cp16s(base + 16384 + so, w2p + (size_t)r * F_DIM + k0 + cc * 8);
        }
        cp_commit();
    };

    float acc[2][8][4];
#pragma unroll
    for (int a = 0; a < 2; ++a)
#pragma unroll
        for (int b = 0; b < 8; ++b)
#pragma unroll
            for (int c = 0; c < 4; ++c) acc[a][b][c] = 0.f;

    const int sx  = lane & 7;
    const int hiA = lane >> 4;
    const int rA  = wm * 32 + (lane & 15);
    const int hiB = (lane >> 3) & 1;
    const int rB  = wn * 64 + ((lane >> 4) & 1) * 8 + (lane & 7);
    const uint32_t aRow0 = (uint32_t)(rA << 7), aRow1 = (uint32_t)((rA + 16) << 7);
    uint32_t bRow[4];
#pragma unroll
    for (int i = 0; i < 4; ++i) bRow[i] = (uint32_t)((rB + i * 16) << 7);

    auto compute_stage = [&](int buf) {
        const uint32_t base = dataB + (uint32_t)buf * G_STAGE;
        const uint32_t Ab = base, Bb = base + 16384;
#pragma unroll
        for (int kk = 0; kk < 4; ++kk) {
            const uint32_t ao = (uint32_t)(((2 * kk + hiA) ^ sx) << 4);
            const uint32_t bo = (uint32_t)(((2 * kk + hiB) ^ sx) << 4);
            uint32_t a[2][4];
            ldsm4(a[0], Ab + aRow0 + ao);
            ldsm4(a[1], Ab + aRow1 + ao);
            uint32_t bf[4][4];
#pragma unroll
            for (int i16 = 0; i16 < 4; ++i16)
                ldsm4(bf[i16], Bb + bRow[i16] + bo);
#pragma unroll
            for (int im = 0; im < 2; ++im)
#pragma unroll
                for (int j = 0; j < 8; ++j)
                    mma16816(acc[im][j], a[im],
                             bf[j >> 1][(j & 1) * 2], bf[j >> 1][(j & 1) * 2 + 1]);
        }
    };

    const int NK = F_DIM / KSTAGE;   // 64
    load_stage(0, 0);
    load_stage(1, 1);
    int bc = 0, bl = 2;
#pragma unroll 1
    for (int kt = 0; kt < NK; ++kt) {
        if (kt < NK - 1) cp_wait<1>();
        else             cp_wait<0>();
        __syncthreads();
        if (kt + 2 < NK) {
            load_stage(bl, kt + 2);
            bl = (bl == 2) ? 0 : bl + 1;
        }
        compute_stage(bc);
        bc = (bc == 2) ? 0 : bc + 1;
    }

    const int mbase = mtile * 128 + wm * 32 + (lane >> 2);
    const int dbase = ntile * 128 + wn * 64 + (lane & 3) * 2;
#pragma unroll
    for (int im = 0; im < 2; ++im)
#pragma unroll
        for (int j = 0; j < 8; ++j)
#pragma unroll
            for (int hh = 0; hh < 2; ++hh) {
                int m = mbase + im * 16 + hh * 8;
                if (m < cnt) {
                    float2 v;
                    v.x = acc[im][j][hh * 2];
                    v.y = acc[im][j][hh * 2 + 1];
                    *reinterpret_cast<float2*>(
                        &g_ys[(size_t)(off + m) * D_DIM + dbase + j * 8]) = v;
                }
            }
}

// ---------------- combine (residual + weighted expert outputs) + counter reset ----
__global__ void __launch_bounds__(256) combine_kernel(const float* __restrict__ x,
                                                      float* __restrict__ out) {
    const int t = blockIdx.x;
    if (blockIdx.x == 0 && threadIdx.x < E_EXP) g_cnt[threadIdx.x] = 0;  // reset for next call
    const int s0 = g_slot[2 * t], s1 = g_slot[2 * t + 1];
    const float g0 = g_gw[2 * t], g1 = g_gw[2 * t + 1];
    const int d = threadIdx.x * 4;
    float4 xv = *reinterpret_cast<const float4*>(x + (size_t)t * D_DIM + d);
    float4 y0 = *reinterpret_cast<const float4*>(g_ys + (size_t)s0 * D_DIM + d);
    float4 y1 = *reinterpret_cast<const float4*>(g_ys + (size_t)s1 * D_DIM + d);
    float4 o;
    o.x = xv.x + g0 * y0.x + g1 * y1.x;
    o.y = xv.y + g0 * y0.y + g1 * y1.y;
    o.z = xv.z + g0 * y0.z + g1 * y1.z;
    o.w = xv.w + g0 * y0.w + g1 * y1.w;
    *reinterpret_cast<float4*>(out + (size_t)t * D_DIM + d) = o;
}

// ---------------- launch (linear, single stream) ----------------
extern "C" void kernel_launch(void* const* d_in, const int* in_sizes, int n_in,
                              void* d_out, int out_size) {
    (void)in_sizes; (void)n_in; (void)out_size;
    const float* x      = (const float*)d_in[0];
    const float* gate_w = (const float*)d_in[1];
    const float* ln_w   = (const float*)d_in[2];
    const float* w1     = (const float*)d_in[3];
    const float* w3     = (const float*)d_in[4];
    const float* w2     = (const float*)d_in[5];
    float* out = (float*)d_out;

    cudaFuncSetAttribute(gemm1_kernel, cudaFuncAttributeMaxDynamicSharedMemorySize, G_SMEM);
    cudaFuncSetAttribute(gemm2_kernel, cudaFuncAttributeMaxDynamicSharedMemorySize, G_SMEM);

    gate_conv13_kernel<<<GATE_BLOCKS + C13_BLOCKS, 256>>>(x, gate_w, w1, w3, ln_w); // 0
    scan_scatter_kernel<<<1, 1024>>>();                                             // 1
    gemm1_kernel<<<G1_TILES + C2_BLOCKS, 256, G_SMEM>>>(w2);                        // 2
    gemm2_kernel<<<dim3(D_DIM / 128, T_TOK / 128, E_EXP), 256, G_SMEM>>>();         // 3
    combine_kernel<<<T_TOK, 256>>>(x, out);                                         // 4
}

// round 17
// speedup vs baseline: 1.5260x; 1.0002x over previous
#include <cuda_runtime.h>
#include <cuda_bf16.h>
#include <stdint.h>

#define E_EXP 8
#define D_DIM 1024
#define F_DIM 4096
#define T_TOK 4096
#define NSLOT (T_TOK * 2)

// ---------------- scratch (static __device__ arrays; no allocation) ----------------
__device__ __nv_bfloat16 g_xnb[(size_t)T_TOK * D_DIM];          // normalized x, bf16
__device__ __nv_bfloat16 g_w1b[(size_t)E_EXP * F_DIM * D_DIM];  // bf16(w1 * ln_w)
__device__ __nv_bfloat16 g_w3b[(size_t)E_EXP * F_DIM * D_DIM];  // bf16(w3 * ln_w)
__device__ __nv_bfloat16 g_w2b[(size_t)E_EXP * D_DIM * F_DIM];  // bf16(w2)
__device__ __nv_bfloat16 g_h[(size_t)NSLOT * F_DIM];            // gated activations
__device__ float         g_ys[(size_t)NSLOT * D_DIM];           // per-slot FFN output
__device__ int   g_cnt[E_EXP];     // zero at load; re-zeroed by combine each call
__device__ int   g_off[E_EXP];
__device__ int   g_perm[NSLOT];
__device__ int   g_tokE[NSLOT];
__device__ int   g_slot[NSLOT];
__device__ float g_gw[NSLOT];

// ---------------- small helpers ----------------
__device__ __forceinline__ void cp16s(uint32_t dst, const void* src) {
    asm volatile("cp.async.cg.shared.global [%0], [%1], 16;\n" :: "r"(dst), "l"(src));
}
__device__ __forceinline__ void cp_commit() { asm volatile("cp.async.commit_group;\n" ::: "memory"); }
template <int N>
__device__ __forceinline__ void cp_wait() { asm volatile("cp.async.wait_group %0;\n" :: "n"(N) : "memory"); }

__device__ __forceinline__ void ldsm4(uint32_t* r, uint32_t a) {
    asm volatile("ldmatrix.sync.aligned.m8n8.x4.shared.b16 {%0,%1,%2,%3}, [%4];\n"
                 : "=r"(r[0]), "=r"(r[1]), "=r"(r[2]), "=r"(r[3]) : "r"(a));
}
__device__ __forceinline__ void mma16816(float* c, const uint32_t* a, uint32_t b0, uint32_t b1) {
    asm volatile(
        "mma.sync.aligned.m16n8k16.row.col.f32.bf16.bf16.f32 "
        "{%0,%1,%2,%3}, {%4,%5,%6,%7}, {%8,%9}, {%0,%1,%2,%3};\n"
        : "+f"(c[0]), "+f"(c[1]), "+f"(c[2]), "+f"(c[3])
        : "r"(a[0]), "r"(a[1]), "r"(a[2]), "r"(a[3]), "r"(b0), "r"(b1));
}
__device__ __forceinline__ float siluf(float v) { return v / (1.f + __expf(-v)); }

// conv13 body: fold ln into w1/w3, fp32 -> bf16, for chunk `sub` (0..4095), NT threads
template <int NT>
__device__ __forceinline__ void conv13_chunk(int sub, int tid,
                                             const float* __restrict__ w1,
                                             const float* __restrict__ w3,
                                             const float* __restrict__ ln) {
    const int e = sub >> 9;
    const int chunk = sub & 511;
    const size_t base = ((size_t)e << 22) + ((size_t)chunk << 13);   // e*F*D + chunk*8192
    const int t4 = tid * 4;
#pragma unroll
    for (int i = 0; i < 8192 / (NT * 4); ++i) {
        size_t idx = base + (size_t)i * (NT * 4) + t4;
        int d = (int)(idx & (D_DIM - 1));
        float4 l = __ldg(reinterpret_cast<const float4*>(ln + (size_t)e * D_DIM + d));
        float4 a = __ldg(reinterpret_cast<const float4*>(w1 + idx));
        float4 b = __ldg(reinterpret_cast<const float4*>(w3 + idx));
        __nv_bfloat162 a0 = __floats2bfloat162_rn(a.x * l.x, a.y * l.y);
        __nv_bfloat162 a1 = __floats2bfloat162_rn(a.z * l.z, a.w * l.w);
        __nv_bfloat162 b0 = __floats2bfloat162_rn(b.x * l.x, b.y * l.y);
        __nv_bfloat162 b1 = __floats2bfloat162_rn(b.z * l.z, b.w * l.w);
        uint2 ua, ub;
        ua.x = *reinterpret_cast<uint32_t*>(&a0); ua.y = *reinterpret_cast<uint32_t*>(&a1);
        ub.x = *reinterpret_cast<uint32_t*>(&b0); ub.y = *reinterpret_cast<uint32_t*>(&b1);
        *reinterpret_cast<uint2*>(g_w1b + idx) = ua;
        *reinterpret_cast<uint2*>(g_w3b + idx) = ub;
    }
}

// ---------------- kernel 0: gating/rmsnorm (blocks 0..511) + conv13 experts 4-7 ----------------
// conv13 output is first read by gemm1 (a later launch) — pure grid packing, no dependency.
#define GATE_BLOCKS 512
#define C13A_BLOCKS 2048
__global__ void __launch_bounds__(256) gate_conv13a_kernel(const float* __restrict__ x,
                                                           const float* __restrict__ gw,
                                                           const float* __restrict__ w1,
                                                           const float* __restrict__ w3,
                                                           const float* __restrict__ ln) {
    __shared__ float s_gw[E_EXP * D_DIM];       // 32 KB (gate path only)
    const int tid = threadIdx.x;

    if (blockIdx.x >= GATE_BLOCKS) {
        // experts 4..7, descending so e4 (needed earliest among these) converts last
        const int sub = 4095 - (int)(blockIdx.x - GATE_BLOCKS);     // 4095..2048
        conv13_chunk<256>(sub, tid, w1, w3, ln);
        return;
    }

    // ---- gate role ----
    const int wid = tid >> 5, lane = tid & 31;
#pragma unroll
    for (int i = 0; i < 8; ++i) {
        int idx = (i * 256 + tid) * 4;
        *reinterpret_cast<float4*>(s_gw + idx) =
            *reinterpret_cast<const float4*>(gw + idx);
    }
    __syncthreads();

    const int t = blockIdx.x * 8 + wid;
    float xr[32];
    float ss = 0.f;
    const float* xp = x + (size_t)t * D_DIM + lane;
#pragma unroll
    for (int i = 0; i < 32; ++i) { xr[i] = xp[i * 32]; ss += xr[i] * xr[i]; }
    float sc[8];
#pragma unroll
    for (int e = 0; e < 8; ++e) {
        const float* gp = s_gw + e * D_DIM + lane;
        float s = 0.f;
#pragma unroll
        for (int i = 0; i < 32; ++i) s += xr[i] * gp[i * 32];
        sc[e] = s;
    }
#pragma unroll
    for (int o = 16; o > 0; o >>= 1) {
        ss += __shfl_xor_sync(0xffffffffu, ss, o);
#pragma unroll
        for (int e = 0; e < 8; ++e) sc[e] += __shfl_xor_sync(0xffffffffu, sc[e], o);
    }
    const float inv = rsqrtf(ss * (1.f / D_DIM) + 1e-6f);
    __nv_bfloat16* xo = g_xnb + (size_t)t * D_DIM + lane;
#pragma unroll
    for (int i = 0; i < 32; ++i) xo[i * 32] = __float2bfloat16(xr[i] * inv);

    if (lane == 0) {
        int i0 = 0; float v0 = sc[0];
#pragma unroll
        for (int e = 1; e < 8; ++e) if (sc[e] > v0) { v0 = sc[e]; i0 = e; }
        int i1 = (i0 == 0) ? 1 : 0; float v1 = sc[i1];
#pragma unroll
        for (int e = 0; e < 8; ++e)
            if (e != i0 && sc[e] > v1) { v1 = sc[e]; i1 = e; }
        const float e1 = __expf(v1 - v0);
        const float z  = 1.f + e1;
        g_tokE[2 * t] = i0; g_tokE[2 * t + 1] = i1;
        g_gw[2 * t] = 1.f / z; g_gw[2 * t + 1] = e1 / z;
        atomicAdd(&g_cnt[i0], 1);
        atomicAdd(&g_cnt[i1], 1);
    }
}

// ---------------- kernel 1: scan+scatter (block 0) + conv13 experts 0-3 ----------------
#define C13B_BLOCKS 2048
__global__ void __launch_bounds__(1024) scan_conv13b_kernel(const float* __restrict__ w1,
                                                            const float* __restrict__ w3,
                                                            const float* __restrict__ ln) {
    const int tid = threadIdx.x;
    if (blockIdx.x > 0) {
        // experts 3..0, descending so e0 (first consumed by gemm1) converts last (L2-hot)
        const int sub = (C13B_BLOCKS - 1) - (int)(blockIdx.x - 1);   // 2047..0
        conv13_chunk<1024>(sub, tid, w1, w3, ln);
        return;
    }
    // ---- scan + scatter role (single block) ----
    __shared__ int s_cur[E_EXP];
    if (tid == 0) {
        int s = 0;
        for (int e = 0; e < E_EXP; ++e) { g_off[e] = s; s_cur[e] = s; s += g_cnt[e]; }
    }
    __syncthreads();
    for (int t = tid; t < T_TOK; t += 1024) {
#pragma unroll
        for (int k = 0; k < 2; ++k) {
            int e = g_tokE[2 * t + k];
            int s = atomicAdd(&s_cur[e], 1);
            g_perm[s] = t;
            g_slot[2 * t + k] = s;
        }
    }
}

// ================= GEMM settings (R8-proven: KSTAGE=64, NBUF=3, 2 CTAs/SM) =================
#define KSTAGE 64
#define NBUF   3
#define G_STAGE 32768
#define G_SMEM  (1024 + NBUF * G_STAGE)
#define G1_TILES (64 * 32 * 8)     // ntile x mtile x expert = 16384
#define C2_BLOCKS 4096

// ---------------- kernel 2: GEMM1 tiles (0..16383) + conv2 (16384..20479) ----------------
__global__ void __launch_bounds__(256, 2) gemm1_kernel(const float* __restrict__ w2) {
    extern __shared__ __align__(128) char smem[];
    const int bid = blockIdx.x;
    const int tid = threadIdx.x;

    if (bid >= G1_TILES) {
        // conv2 role: w2 fp32 -> bf16 (consumed only by gemm2, the next launch)
        const int sub = bid - G1_TILES;
        const size_t base = (size_t)sub << 13;
        const int t4 = tid * 4;
#pragma unroll
        for (int i = 0; i < 8; ++i) {
            size_t idx = base + (size_t)i * 1024 + t4;
            float4 a = __ldg(reinterpret_cast<const float4*>(w2 + idx));
            __nv_bfloat162 a0 = __floats2bfloat162_rn(a.x, a.y);
            __nv_bfloat162 a1 = __floats2bfloat162_rn(a.z, a.w);
            uint2 ua;
            ua.x = *reinterpret_cast<uint32_t*>(&a0); ua.y = *reinterpret_cast<uint32_t*>(&a1);
            *reinterpret_cast<uint2*>(g_w2b + idx) = ua;
        }
        return;
    }

    // ---- gemm1 tile role ----
    const int e = bid >> 11;
    const int rem = bid & 2047;
    const int mtile = rem >> 6;
    const int ntile = rem & 63;
    const int cnt = g_cnt[e];
    if (mtile * 128 >= cnt) return;
    const int off = g_off[e];
    const int lane = tid & 31;
    const int w = tid >> 5;
    const int wm = w & 3, wn = w >> 2;

    int* rows = (int*)smem;
    const uint32_t sb = (uint32_t)__cvta_generic_to_shared(smem);
    const uint32_t dataB = sb + 1024;

    if (tid < 128) {
        int m = mtile * 128 + tid;
        rows[tid] = g_perm[off + (m < cnt ? m : cnt - 1)];
    }
    __syncthreads();

    const __nv_bfloat16* w1p = g_w1b + ((size_t)e * F_DIM + (size_t)ntile * 64) * D_DIM;
    const __nv_bfloat16* w3p = g_w3b + ((size_t)e * F_DIM + (size_t)ntile * 64) * D_DIM;

    const int rr = tid >> 3;
    const int cc = tid & 7;
    const uint32_t swoff = (uint32_t)cc << 4;

    auto load_stage = [&](int buf, int kt) {
        const uint32_t base = dataB + (uint32_t)buf * G_STAGE;
        const int k0 = kt * KSTAGE;
#pragma unroll
        for (int p = 0; p < 4; ++p) {            // A: 128 rows
            int r = p * 32 + rr;
            uint32_t so = (uint32_t)(r << 7) + (swoff ^ ((uint32_t)(r & 7) << 4));
            cp16s(base + so, g_xnb + (size_t)rows[r] * D_DIM + k0 + cc * 8);
        }
#pragma unroll
        for (int p = 0; p < 2; ++p) {            // B1, B3: 64 rows each
            int r = p * 32 + rr;
            uint32_t so = (uint32_t)(r << 7) + (swoff ^ ((uint32_t)(r & 7) << 4));
            cp16s(base + 16384 + so, w1p + (size_t)r * D_DIM + k0 + cc * 8);
            cp16s(base + 24576 + so, w3p + (size_t)r * D_DIM + k0 + cc * 8);
        }
        cp_commit();
    };

    float acc1[2][4][4], acc3[2][4][4];
#pragma unroll
    for (int a = 0; a < 2; ++a)
#pragma unroll
        for (int b = 0; b < 4; ++b)
#pragma unroll
            for (int c = 0; c < 4; ++c) { acc1[a][b][c] = 0.f; acc3[a][b][c] = 0.f; }

    const int sx  = lane & 7;
    const int hiA = lane >> 4;
    const int rA  = wm * 32 + (lane & 15);
    const int hiB = (lane >> 3) & 1;
    const int rB  = wn * 32 + ((lane >> 4) & 1) * 8 + (lane & 7);
    const uint32_t aRow0 = (uint32_t)(rA << 7), aRow1 = (uint32_t)((rA + 16) << 7);
    const uint32_t bRow0 = (uint32_t)(rB << 7), bRow1 = (uint32_t)((rB + 16) << 7);

    auto compute_stage = [&](int buf) {
        const uint32_t base = dataB + (uint32_t)buf * G_STAGE;
        const uint32_t Ab = base, B1b = base + 16384, B3b = base + 24576;
#pragma unroll
        for (int kk = 0; kk < 4; ++kk) {
            const uint32_t ao = (uint32_t)(((2 * kk + hiA) ^ sx) << 4);
            const uint32_t bo = (uint32_t)(((2 * kk + hiB) ^ sx) << 4);
            uint32_t a[2][4];
            ldsm4(a[0], Ab + aRow0 + ao);
            ldsm4(a[1], Ab + aRow1 + ao);
            uint32_t b1f[2][4], b3f[2][4];
            ldsm4(b1f[0], B1b + bRow0 + bo);
            ldsm4(b1f[1], B1b + bRow1 + bo);
            ldsm4(b3f[0], B3b + bRow0 + bo);
            ldsm4(b3f[1], B3b + bRow1 + bo);
#pragma unroll
            for (int im = 0; im < 2; ++im)
#pragma unroll
                for (int j = 0; j < 4; ++j) {
                    mma16816(acc1[im][j], a[im],
                             b1f[j >> 1][(j & 1) * 2], b1f[j >> 1][(j & 1) * 2 + 1]);
                    mma16816(acc3[im][j], a[im],
                             b3f[j >> 1][(j & 1) * 2], b3f[j >> 1][(j & 1) * 2 + 1]);
                }
        }
    };

    const int NK = D_DIM / KSTAGE;   // 16
    load_stage(0, 0);
    load_stage(1, 1);
    int bc = 0, bl = 2;
#pragma unroll 1
    for (int kt = 0; kt < NK; ++kt) {
        if (kt < NK - 1) cp_wait<1>();
        else             cp_wait<0>();
        __syncthreads();
        if (kt + 2 < NK) {
            load_stage(bl, kt + 2);
            bl = (bl == 2) ? 0 : bl + 1;
        }
        compute_stage(bc);
        bc = (bc == 2) ? 0 : bc + 1;
    }

    const int mbase = mtile * 128 + wm * 32 + (lane >> 2);
    const int fbase = ntile * 64 + wn * 32 + (lane & 3) * 2;
#pragma unroll
    for (int im = 0; im < 2; ++im)
#pragma unroll
        for (int j = 0; j < 4; ++j)
#pragma unroll
            for (int hh = 0; hh < 2; ++hh) {
                int m = mbase + im * 16 + hh * 8;
                if (m < cnt) {
                    float v0 = siluf(acc1[im][j][hh * 2])     * acc3[im][j][hh * 2];
                    float v1 = siluf(acc1[im][j][hh * 2 + 1]) * acc3[im][j][hh * 2 + 1];
                    *reinterpret_cast<__nv_bfloat162*>(
                        &g_h[(size_t)(off + m) * F_DIM + fbase + j * 8]) =
                        __floats2bfloat162_rn(v0, v1);
                }
            }
}

// ---------------- GEMM2 (h @ w2^T -> ys) ----------------
// CTA tile: M=128, N=128. 8 warps (4m x 2n), warp tile 32x64. Experts reversed.
__global__ void __launch_bounds__(256, 2) gemm2_kernel() {
    extern __shared__ __align__(128) char smem[];
    const int e = E_EXP - 1 - blockIdx.z;
    const int cnt = g_cnt[e];
    const int mtile = blockIdx.y;
    if (mtile * 128 >= cnt) return;
    const int ntile = blockIdx.x;     // 0..7
    const int off = g_off[e];
    const int tid = threadIdx.x;
    const int lane = tid & 31;
    const int w = tid >> 5;
    const int wm = w & 3, wn = w >> 2;

    int* rowsA = (int*)smem;
    const uint32_t sb = (uint32_t)__cvta_generic_to_shared(smem);
    const uint32_t dataB = sb + 1024;

    if (tid < 128) {
        int m = mtile * 128 + tid;
        rowsA[tid] = off + (m < cnt ? m : cnt - 1);
    }
    __syncthreads();

    const __nv_bfloat16* w2p = g_w2b + ((size_t)e * D_DIM + (size_t)ntile * 128) * F_DIM;

    const int rr = tid >> 3;
    const int cc = tid & 7;
    const uint32_t swoff = (uint32_t)cc << 4;

    auto load_stage = [&](int buf, int kt) {
        const uint32_t base = dataB + (uint32_t)buf * G_STAGE;
        const int k0 = kt * KSTAGE;
#pragma unroll
        for (int p = 0; p < 4; ++p) {            // A: 128 rows of h
            int r = p * 32 + rr;
            uint32_t so = (uint32_t)(r << 7) + (swoff ^ ((uint32_t)(r & 7) << 4));
            cp16s(base + so, g_h + (size_t)rowsA[r] * F_DIM + k0 + cc * 8);
        }
#pragma unroll
        for (int p = 0; p < 4; ++p) {            // B: 128 rows of w2
            int r = p * 32 + rr;
            uint32_t so = (uint32_t)(r << 7) + (swoff ^ ((uint32_t)(r & 7) << 4));
            cp16s(base + 16384 + so, w2p + (size_t)r * F_DIM + k0 + cc * 8);
        }
        cp_commit();
    };

    float acc[2][8][4];
#pragma unroll
    for (int a = 0; a < 2; ++a)
#pragma unroll
        for (int b = 0; b < 8; ++b)
#pragma unroll
            for (int c = 0; c < 4; ++c) acc[a][b][c] = 0.f;

    const int sx  = lane & 7;
    const int hiA = lane >> 4;
    const int rA  = wm * 32 + (lane & 15);
    const int hiB = (lane >> 3) & 1;
    const int rB  = wn * 64 + ((lane >> 4) & 1) * 8 + (lane & 7);
    const uint32_t aRow0 = (uint32_t)(rA << 7), aRow1 = (uint32_t)((rA + 16) << 7);
    uint32_t bRow[4];
#pragma unroll
    for (int i = 0; i < 4; ++i) bRow[i] = (uint32_t)((rB + i * 16) << 7);

    auto compute_stage = [&](int buf) {
        const uint32_t base = dataB + (uint32_t)buf * G_STAGE;
        const uint32_t Ab = base, Bb = base + 16384;
#pragma unroll
        for (int kk = 0; kk < 4; ++kk) {
            const uint32_t ao = (uint32_t)(((2 * kk + hiA) ^ sx) << 4);
            const uint32_t bo = (uint32_t)(((2 * kk + hiB) ^ sx) << 4);
            uint32_t a[2][4];
            ldsm4(a[0], Ab + aRow0 + ao);
            ldsm4(a[1], Ab + aRow1 + ao);
            uint32_t bf[4][4];
#pragma unroll
            for (int i16 = 0; i16 < 4; ++i16)
                ldsm4(bf[i16], Bb + bRow[i16] + bo);
#pragma unroll
            for (int im = 0; im < 2; ++im)
#pragma unroll
                for (int j = 0; j < 8; ++j)
                    mma16816(acc[im][j], a[im],
                             bf[j >> 1][(j & 1) * 2], bf[j >> 1][(j & 1) * 2 + 1]);
        }
    };

    const int NK = F_DIM / KSTAGE;   // 64
    load_stage(0, 0);
    load_stage(1, 1);
    int bc = 0, bl = 2;
#pragma unroll 1
    for (int kt = 0; kt < NK; ++kt) {
        if (kt < NK - 1) cp_wait<1>();
        else             cp_wait<0>();
        __syncthreads();
        if (kt + 2 < NK) {
            load_stage(bl, kt + 2);
            bl = (bl == 2) ? 0 : bl + 1;
        }
        compute_stage(bc);
        bc = (bc == 2) ? 0 : bc + 1;
    }

    const int mbase = mtile * 128 + wm * 32 + (lane >> 2);
    const int dbase = ntile * 128 + wn * 64 + (lane & 3) * 2;
#pragma unroll
    for (int im = 0; im < 2; ++im)
#pragma unroll
        for (int j = 0; j < 8; ++j)
#pragma unroll
            for (int hh = 0; hh < 2; ++hh) {
                int m = mbase + im * 16 + hh * 8;
                if (m < cnt) {
                    float2 v;
                    v.x = acc[im][j][hh * 2];
                    v.y = acc[im][j][hh * 2 + 1];
                    *reinterpret_cast<float2*>(
                        &g_ys[(size_t)(off + m) * D_DIM + dbase + j * 8]) = v;
                }
            }
}

// ---------------- combine (residual + weighted expert outputs) + counter reset ----
__global__ void __launch_bounds__(256) combine_kernel(const float* __restrict__ x,
                                                      float* __restrict__ out) {
    const int t = blockIdx.x;
    if (blockIdx.x == 0 && threadIdx.x < E_EXP) g_cnt[threadIdx.x] = 0;  // reset for next call
    const int s0 = g_slot[2 * t], s1 = g_slot[2 * t + 1];
    const float g0 = g_gw[2 * t], g1 = g_gw[2 * t + 1];
    const int d = threadIdx.x * 4;
    float4 xv = *reinterpret_cast<const float4*>(x + (size_t)t * D_DIM + d);
    float4 y0 = *reinterpret_cast<const float4*>(g_ys + (size_t)s0 * D_DIM + d);
    float4 y1 = *reinterpret_cast<const float4*>(g_ys + (size_t)s1 * D_DIM + d);
    float4 o;
    o.x = xv.x + g0 * y0.x + g1 * y1.x;
    o.y = xv.y + g0 * y0.y + g1 * y1.y;
    o.z = xv.z + g0 * y0.z + g1 * y1.z;
    o.w = xv.w + g0 * y0.w + g1 * y1.w;
    *reinterpret_cast<float4*>(out + (size_t)t * D_DIM + d) = o;
}

// ---------------- launch (linear, single stream) ----------------
extern "C" void kernel_launch(void* const* d_in, const int* in_sizes, int n_in,
                              void* d_out, int out_size) {
    (void)in_sizes; (void)n_in; (void)out_size;
    const float* x      = (const float*)d_in[0];
    const float* gate_w = (const float*)d_in[1];
    const float* ln_w   = (const float*)d_in[2];
    const float* w1     = (const float*)d_in[3];
    const float* w3     = (const float*)d_in[4];
    const float* w2     = (const float*)d_in[5];
    float* out = (float*)d_out;

    cudaFuncSetAttribute(gemm1_kernel, cudaFuncAttributeMaxDynamicSharedMemorySize, G_SMEM);
    cudaFuncSetAttribute(gemm2_kernel, cudaFuncAttributeMaxDynamicSharedMemorySize, G_SMEM);

    gate_conv13a_kernel<<<GATE_BLOCKS + C13A_BLOCKS, 256>>>(x, gate_w, w1, w3, ln_w); // 0
    scan_conv13b_kernel<<<1 + C13B_BLOCKS, 1024>>>(w1, w3, ln_w);                     // 1
    gemm1_kernel<<<G1_TILES + C2_BLOCKS, 256, G_SMEM>>>(w2);                          // 2
    gemm2_kernel<<<dim3(D_DIM / 128, T_TOK / 128, E_EXP), 256, G_SMEM>>>();           // 3
    combine_kernel<<<T_TOK, 256>>>(x, out);                                           // 4
}